// round 15
// baseline (speedup 1.0000x reference)
#include <cuda_runtime.h>
#include <cuda_bf16.h>
#include <math.h>

typedef unsigned long long u64;
typedef unsigned int u32;

// ---------------- problem constants ----------------
static const int NSUP  = 115;
static const int NQRY  = 23;
static const int NTOT  = 138;
static const int NCLS  = 23;

// ---------------- device scratch ----------------
__device__ float g_buf0[(size_t)NTOT*64*128*128];
__device__ float g_buf1[(size_t)NTOT*64*64*64];
__device__ __nv_bfloat16 g_ahi [(size_t)NTOT*128*130*64];  // conv2 input transposed, hi
__device__ __nv_bfloat16 g_alo [(size_t)NTOT*128*130*64];  // lo
__device__ __nv_bfloat16 g_ahi2[(size_t)NTOT*64*66*64];    // conv3 input transposed (borders stay 0)
__device__ __nv_bfloat16 g_alo2[(size_t)NTOT*64*66*64];
__device__ __nv_bfloat16 g_wb  [2*18*64*64];               // conv2+conv3 weights [L][tp][ci(k)][oc]
__device__ float g_cat [(size_t)NTOT*2048];
__device__ float g_tmp [(size_t)NTOT*1024];
__device__ float g_h2  [(size_t)NTOT*1024];
__device__ float g_feat[(size_t)NTOT*1024];
__device__ float g_agg [(size_t)NTOT*1024];
__device__ float g_cnt [NTOT];
__device__ float g_b   [NQRY*NSUP];
__device__ float g_dis [NQRY*NCLS];

// ---------------- packed f32x2 helpers ----------------
__device__ __forceinline__ u64 pk2(float x, float y){
    u64 r; asm("mov.b64 %0, {%1, %2};" : "=l"(r) : "f"(x), "f"(y)); return r;
}
__device__ __forceinline__ void fma2(u64 &d, u64 a, u64 b){
    asm("fma.rn.f32x2 %0, %1, %2, %0;" : "+l"(d) : "l"(a), "l"(b));
}
__device__ __forceinline__ float2 up2(u64 a){
    float2 r; asm("mov.b64 {%0, %1}, %2;" : "=f"(r.x), "=f"(r.y) : "l"(a)); return r;
}
__device__ __forceinline__ u64 cmp2(u64 a, u64 b){ return (a >> 32) | (b << 32); }

// ---------------- warp-mma helpers ----------------
__device__ __forceinline__ void ldsm4(u32* r, u32 addr){
    asm volatile("ldmatrix.sync.aligned.m8n8.x4.shared.b16 {%0,%1,%2,%3}, [%4];"
        : "=r"(r[0]),"=r"(r[1]),"=r"(r[2]),"=r"(r[3]) : "r"(addr));
}
__device__ __forceinline__ void ldsm4t(u32* r, u32 addr){
    asm volatile("ldmatrix.sync.aligned.m8n8.x4.trans.shared.b16 {%0,%1,%2,%3}, [%4];"
        : "=r"(r[0]),"=r"(r[1]),"=r"(r[2]),"=r"(r[3]) : "r"(addr));
}
#define MMA(dd, a, b0, b1) \
    asm volatile("mma.sync.aligned.m16n8k16.row.col.f32.bf16.bf16.f32 " \
        "{%0,%1,%2,%3},{%4,%5,%6,%7},{%8,%9},{%0,%1,%2,%3};" \
        : "+f"((dd)[0]),"+f"((dd)[1]),"+f"((dd)[2]),"+f"((dd)[3]) \
        : "r"((a)[0]),"r"((a)[1]),"r"((a)[2]),"r"((a)[3]), "r"(b0),"r"(b1))

// ---------------- prep: weight split for conv2+conv3, layout [L][tp][ci(k)][oc] ----------------
__global__ void wb2_kernel(const float* __restrict__ cwr, __nv_bfloat16* __restrict__ wbp)
{
    int i = blockIdx.x*256 + threadIdx.x;          // over 2*18*64*64
    if (i >= 2*73728) return;
    int L = i / 73728;
    int r = i % 73728;
    int oc = r & 63, ci = (r>>6)&63, tp = r>>12;
    int tap = tp >> 1, part = tp & 1;
    float v = cwr[(size_t)L*36864 + (oc*64 + ci)*9 + tap];
    __nv_bfloat16 h = __float2bfloat16(v);
    wbp[i] = (part == 0) ? h : __float2bfloat16(v - __bfloat162float(h));
}

// ---------------- prep: transpose conv1 out to [img][y][x+1][ci] bf16 hi/lo ----------------
__global__ void tr_kernel(const float* __restrict__ in,
                          __nv_bfloat16* __restrict__ ahi,
                          __nv_bfloat16* __restrict__ alo)
{
    __shared__ float sT[64][133];
    int y = blockIdx.x, img = blockIdx.y;
    const float* src = in + (size_t)img*64*16384 + y*128;
    for (int e = threadIdx.x; e < 64*130; e += 256){
        int ci = e / 130, xi = e - ci*130;
        int xs = xi - 1;
        float v = ((unsigned)xs < 128u) ? src[(size_t)ci*16384 + xs] : 0.f;
        sT[ci][xi] = v;
    }
    __syncthreads();
    size_t ob = (size_t)(img*128 + y)*130*64;
    for (int e = threadIdx.x; e < 130*64; e += 256){
        int xi = e >> 6, ci = e & 63;
        float v = sT[ci][xi];
        __nv_bfloat16 h = __float2bfloat16(v);
        ahi[ob + e] = h;
        alo[ob + e] = __float2bfloat16(v - __bfloat162float(h));
    }
}

// ---------------- tconv2: small-CTA conv3x3+bias+relu+pool2 via mma.sync, 2 CTAs/SM ----------------
// CTA = 4 warps, 64 x-cols, 16 oc. grid.x = 4 oc-quarters * (IN_H/64) x-halves.
// smem: B [18 tp][64 k][48B] = 55296 | A ring 3 slots x 2 parts x (66 x 144B) = 57024 | bias
template<int IN_H, bool OUT_TR>
__global__ void __launch_bounds__(128, 2)
tconv_kernel(const __nv_bfloat16* __restrict__ ahi,
             const __nv_bfloat16* __restrict__ alo,
             const __nv_bfloat16* __restrict__ wbp,
             const float* __restrict__ bias,
             float* __restrict__ outF,
             __nv_bfloat16* __restrict__ outHi,
             __nv_bfloat16* __restrict__ outLo)
{
    constexpr int XCTAS  = IN_H/64;
    constexpr int PH     = IN_H/2;
    constexpr int ROWFULL= (IN_H+2)*32;   // u32 per full row per part
    constexpr int ROWU32 = 66*32;         // 2112 u32 read per row per part
    constexpr int NSTG   = 17;            // ceil(2112/128)
    constexpr u32 SLOT   = 66*144;        // 9504
    constexpr u32 APART  = 3*SLOT;        // 28512

    extern __shared__ __align__(16) unsigned char sm[];
    const u32 SB  = (u32)__cvta_generic_to_shared(sm);
    const u32 SMB = 0;
    const u32 SMA = 55296;
    float* sBias = (float*)(sm + SMA + 2*APART);

    const int tid  = threadIdx.x;
    const int warp = tid >> 5;
    const int t    = tid & 31;
    const int q    = blockIdx.x / XCTAS;       // oc quarter 0..3
    const int xh   = blockIdx.x % XCTAS;       // x half
    const int img  = blockIdx.y;
    const int m0   = warp*16;                  // local conv x base

    // ---- load B: per tp tile [64 k][16 oc], row stride 48B ----
    const u32* wb32 = (const u32*)wbp;
    for (int e = tid; e < 9216; e += 128){
        int oc4 = e & 7, ci = (e>>3)&63, tp = e>>9;
        u32 v = wb32[(tp*64 + ci)*32 + q*8 + oc4];
        *(u32*)(sm + SMB + (u32)tp*3072 + (u32)ci*48 + (u32)oc4*4) = v;
    }
    if (tid < 16) sBias[t] = bias[q*16 + t];

    const u32* srcH = (const u32*)(ahi + (size_t)img*IN_H*(IN_H+2)*64) + xh*2048;
    const u32* srcL = (const u32*)(alo + (size_t)img*IN_H*(IN_H+2)*64) + xh*2048;

    u32 fH[NSTG], fL[NSTG];
    auto stage = [&](int j){
        #pragma unroll
        for (int i = 0; i < NSTG; i++){
            int e = tid + i*128;
            if (e < ROWU32){
                fH[i] = srcH[(size_t)j*ROWFULL + e];
                fL[i] = srcL[(size_t)j*ROWFULL + e];
            }
        }
    };
    auto sts = [&](int j){
        u32 slotB = SMA + (u32)((j+1)%3)*SLOT;
        #pragma unroll
        for (int i = 0; i < NSTG; i++){
            int e = tid + i*128;
            if (e < ROWU32){
                int xi = e >> 5, ci2 = e & 31;
                u32 off = slotB + (u32)xi*144 + (u32)ci2*4;
                *(u32*)(sm + off)         = fH[i];
                *(u32*)(sm + off + APART) = fL[i];
            }
        }
    };

    stage(0); sts(0);
    stage(1); sts(1);
    stage(2);
    __syncthreads();

    const u32 laneA = (u32)((t & 15)*144 + (t >> 4)*16);
    const u32 laneB = (u32)((t & 15)*48  + (t >> 4)*16);
    const int quad = t >> 2, qi = t & 3;
    const bool act = ((quad & 1) == 0);
    float* opF = OUT_TR ? nullptr
               : outF + (size_t)img*64*PH*PH + (size_t)q*16*PH*PH;

    float prev[2][4];
    #pragma unroll
    for (int nt=0;nt<2;nt++)
        #pragma unroll
        for (int r=0;r<4;r++) prev[nt][r] = 0.f;

    #pragma unroll 1
    for (int y = 0; y < IN_H; y++){
        float d[2][4];
        #pragma unroll
        for (int nt=0;nt<2;nt++)
            #pragma unroll
            for (int r=0;r<4;r++) d[nt][r] = 0.f;

        #pragma unroll
        for (int dy = 0; dy < 3; dy++){
            int iy = y + dy - 1;
            if ((unsigned)iy >= (unsigned)IN_H) continue;
            u32 slotBase = SB + SMA + (u32)((y+dy)%3)*SLOT;
            #pragma unroll
            for (int dx = 0; dx < 3; dx++){
                int tp = (dy*3+dx)*2;
                u32 aB = slotBase + (u32)(m0+dx)*144 + laneA;
                u32 bB = SB + SMB + (u32)tp*3072 + laneB;
                #pragma unroll
                for (int ks = 0; ks < 4; ks++){
                    u32 aH[4], aL[4], bH[4], bL[4];
                    ldsm4 (aH, aB + ks*32);
                    ldsm4 (aL, aB + APART + ks*32);
                    ldsm4t(bH, bB + ks*768);
                    ldsm4t(bL, bB + 3072 + ks*768);
                    MMA(d[0], aH, bH[0], bH[1]);
                    MMA(d[1], aH, bH[2], bH[3]);
                    MMA(d[0], aH, bL[0], bL[1]);
                    MMA(d[1], aH, bL[2], bL[3]);
                    MMA(d[0], aL, bH[0], bH[1]);
                    MMA(d[1], aL, bH[2], bH[3]);
                }
            }
        }

        // epilogue: x-pair pool via shfl, y-pair via registers
        #pragma unroll
        for (int nt = 0; nt < 2; nt++){
            #pragma unroll
            for (int r = 0; r < 4; r++){
                float v = d[nt][r];
                float p = fmaxf(v, __shfl_xor_sync(0xffffffffu, v, 4));
                if (act){
                    if ((y & 1) == 0){
                        prev[nt][r] = p;
                    } else {
                        int x2l = (m0 + quad + ((r>>1)<<3)) >> 1;    // local 0..31
                        int x2  = xh*32 + x2l;
                        int ocl = nt*8 + (qi<<1) + (r&1);            // 0..15
                        float o = fmaxf(prev[nt][r], p) + sBias[ocl];
                        o = fmaxf(o, 0.f);
                        if (OUT_TR){
                            size_t idx = (((size_t)img*PH + (y>>1))*(PH+2) + x2+1)*64 + q*16 + ocl;
                            __nv_bfloat16 h = __float2bfloat16(o);
                            outHi[idx] = h;
                            outLo[idx] = __float2bfloat16(o - __bfloat162float(h));
                        } else {
                            opF[(size_t)ocl*PH*PH + ((size_t)(y>>1))*PH + x2] = o;
                        }
                    }
                }
            }
        }

        __syncthreads();
        if (y + 2 < IN_H) sts(y+2);
        if (y + 3 < IN_H) stage(y+3);
        __syncthreads();
    }
}

// ---------------- conv1n (proven) ----------------
__global__ void __launch_bounds__(512, 2)
conv1n_kernel(const float* __restrict__ sx,
              const float* __restrict__ qx,
              const float* __restrict__ w,
              const float* __restrict__ bias,
              float* __restrict__ out)
{
    __shared__ __align__(16) float sTile[3][10][18];
    __shared__ u64 sW[64][27];

    const int tid = threadIdx.x;
    const int img = blockIdx.y;
    const int tx = blockIdx.x & 15;
    const int ty = blockIdx.x >> 4;
    const int gx0 = tx*16, gy0 = ty*8;
    const float* inImg = (img < NSUP) ? sx + (size_t)img*3*65536
                                      : qx + (size_t)(img-NSUP)*3*65536;

    for (int idx = tid; idx < 540; idx += 512){
        int k = idx/180; int rem = idx - k*180;
        int r = rem/18, c = rem - r*18;
        int iy = gy0 - 1 + r, ix = gx0 - 1 + c;
        float v = 0.f;
        if ((unsigned)iy < 256u && (unsigned)ix < 256u)
            v = inImg[k*65536 + iy*256 + ix];
        sTile[k][r][c] = v;
    }
    for (int idx = tid; idx < 1728; idx += 512){
        float v = w[idx];
        sW[idx/27][idx%27] = pk2(v, v);
    }
    __syncthreads();

    const int oc  = tid >> 3;
    const int sid = tid & 7;
    const u64* tbase = (const u64*)sTile;

    u64 acc[8];
    #pragma unroll
    for (int r = 0; r < 8; r++) acc[r] = 0ull;

    #pragma unroll
    for (int ci = 0; ci < 3; ci++){
        u64 wr[9];
        #pragma unroll
        for (int tt = 0; tt < 9; tt++) wr[tt] = sW[oc][ci*9 + tt];
        #pragma unroll
        for (int tr = 0; tr < 10; tr++){
            u64 T0 = tbase[(ci*10 + tr)*9 + sid];
            u64 T2 = tbase[(ci*10 + tr)*9 + sid + 1];
            u64 T1 = cmp2(T0, T2);
            #pragma unroll
            for (int dy = 0; dy < 3; dy++){
                const int r = tr - dy;
                if (r >= 0 && r < 8){
                    fma2(acc[r], T0, wr[dy*3+0]);
                    fma2(acc[r], T1, wr[dy*3+1]);
                    fma2(acc[r], T2, wr[dy*3+2]);
                }
            }
        }
    }

    float b = bias[oc];
    const int pxl = tx*8 + sid;
    const int py0 = ty*4;
    float* op = out + ((size_t)img*64 + oc)*16384;
    #pragma unroll
    for (int i = 0; i < 4; i++){
        float2 a0 = up2(acc[2*i]), a1 = up2(acc[2*i+1]);
        float m = fmaxf(fmaxf(a0.x, a0.y), fmaxf(a1.x, a1.y)) + b;
        op[(py0 + i)*128 + pxl] = fmaxf(m, 0.f);
    }
}

// ---------------- conv64e (proven): triple-buffered FFMA2 conv ----------------
template<int IN_H>
__global__ void __launch_bounds__(512,1)
conv64e_kernel(const float* __restrict__ in,
               const float* __restrict__ w,
               const float* __restrict__ bias,
               float* __restrict__ out,
               int outImgStride)
{
    constexpr int PH    = IN_H/2;
    constexpr int TILES = PH/8;
    constexpr int TI    = 18;
    constexpr int CHUNK = 8;
    constexpr int HH    = IN_H*IN_H;
    constexpr int PKN   = CHUNK*TI*17;
    constexpr int WN    = 64*CHUNK*9;

    extern __shared__ __align__(16) unsigned char smx[];
    u64* sW  = (u64*)smx;
    u64* sPk = (u64*)(smx + 3*(size_t)WN*8);

    const int tid = threadIdx.x;
    const int pos = tid & 31;
    const int ocg = tid >> 5;
    const int pr  = pos & 3;
    const int px  = pos >> 2;
    const int img = blockIdx.y;
    const int tpy = blockIdx.x / TILES, tpx = blockIdx.x % TILES;
    const int cy0 = tpy*16, cx0 = tpx*16;
    const float* inImg = in + (size_t)img*64*HH;

    int  eoff[5];
    bool ep0[5], ep1[5];
    #pragma unroll
    for (int j=0;j<5;j++){
        int e = tid + j*512;
        bool v = e < PKN;
        int ee = v ? e : 0;
        int k = ee/306, rem = ee - k*306;
        int r = rem/17,  s  = rem - r*17;
        int c0 = (s<9) ? 2*s : 2*(s-9)+1;
        int iy = cy0-1+r, ix0 = cx0-1+c0;
        bool rowok = (unsigned)iy < (unsigned)IN_H;
        ep0[j] = v && rowok && (unsigned)ix0     < (unsigned)IN_H;
        ep1[j] = v && rowok && (unsigned)(ix0+1) < (unsigned)IN_H;
        eoff[j] = k*HH + iy*IN_H + ix0;
    }
    int gwoff[9];
    #pragma unroll
    for (int j=0;j<9;j++){
        int we = tid + j*512;
        int oc = we/72, rem = we - oc*72;
        int k = rem/9,  tt  = rem - k*9;
        gwoff[j] = (oc*64 + k)*9 + tt;
    }

    u64 acc[4][4];
    #pragma unroll
    for (int o=0;o<4;o++)
        #pragma unroll
        for (int cc=0;cc<4;cc++) acc[o][cc] = 0ull;

    float f[5][2], wr[9];
    const float* pIn = inImg;
    const float* pW  = w;

    #pragma unroll
    for (int j=0;j<5;j++){
        f[j][0] = ep0[j] ? pIn[eoff[j]]   : 0.f;
        f[j][1] = ep1[j] ? pIn[eoff[j]+1] : 0.f;
    }
    #pragma unroll
    for (int j=0;j<9;j++) wr[j] = pW[gwoff[j]];
    pIn += CHUNK*HH; pW += 72;

    #pragma unroll
    for (int j=0;j<5;j++){
        int e = tid + j*512;
        if (e < PKN) *(float2*)(sPk + e) = make_float2(f[j][0], f[j][1]);
    }
    #pragma unroll
    for (int j=0;j<9;j++)
        *(float2*)(sW + tid + j*512) = make_float2(wr[j], wr[j]);

    #pragma unroll
    for (int j=0;j<5;j++){
        f[j][0] = ep0[j] ? pIn[eoff[j]]   : 0.f;
        f[j][1] = ep1[j] ? pIn[eoff[j]+1] : 0.f;
    }
    #pragma unroll
    for (int j=0;j<9;j++) wr[j] = pW[gwoff[j]];
    pIn += CHUNK*HH; pW += 72;

    __syncthreads();

    int rb = 0, wb = 1;
    #pragma unroll 1
    for (int c = 0; c < 8; c++){
        if (c < 7){
            u64* pkw = sPk + wb*PKN;
            u64* ww  = sW  + wb*WN;
            #pragma unroll
            for (int j=0;j<5;j++){
                int e = tid + j*512;
                if (e < PKN) *(float2*)(pkw + e) = make_float2(f[j][0], f[j][1]);
            }
            #pragma unroll
            for (int j=0;j<9;j++)
                *(float2*)(ww + tid + j*512) = make_float2(wr[j], wr[j]);
        }
        if (c < 6){
            #pragma unroll
            for (int j=0;j<5;j++){
                f[j][0] = ep0[j] ? pIn[eoff[j]]   : 0.f;
                f[j][1] = ep1[j] ? pIn[eoff[j]+1] : 0.f;
            }
            #pragma unroll
            for (int j=0;j<9;j++) wr[j] = pW[gwoff[j]];
            pIn += CHUNK*HH; pW += 72;
        }

        const u64* pkb = sPk + rb*PKN;
        const u64* wbb = sW  + rb*WN;
        #pragma unroll
        for (int k=0;k<CHUNK;k++){
            const u64* prow = pkb + (k*TI + 4*pr)*17;
            u64 P[6][3];
            #pragma unroll
            for (int r=0;r<6;r++){
                P[r][0] = prow[r*17 + px];
                P[r][1] = prow[r*17 + 9 + px];
                P[r][2] = prow[r*17 + px + 1];
            }
            #pragma unroll
            for (int o=0;o<4;o++){
                const u64* wp = wbb + ((ocg*4+o)*8 + k)*9;
                #pragma unroll
                for (int dy=0;dy<3;dy++){
                    u64 w0 = wp[dy*3+0], w1 = wp[dy*3+1], w2 = wp[dy*3+2];
                    #pragma unroll
                    for (int cc=0;cc<4;cc++) fma2(acc[o][cc], P[cc+dy][0], w0);
                    #pragma unroll
                    for (int cc=0;cc<4;cc++) fma2(acc[o][cc], P[cc+dy][1], w1);
                    #pragma unroll
                    for (int cc=0;cc<4;cc++) fma2(acc[o][cc], P[cc+dy][2], w2);
                }
            }
        }

        if (c == 7) break;
        __syncthreads();
        rb = wb; wb = (wb == 2) ? 0 : wb + 1;
    }

    const int gx  = tpx*8 + px;
    const int gy0 = tpy*8 + 2*pr;
    #pragma unroll
    for (int o=0;o<4;o++){
        int oc = ocg*4 + o;
        float b = bias[oc];
        float2 a0 = up2(acc[o][0]), a1 = up2(acc[o][1]);
        float2 a2 = up2(acc[o][2]), a3 = up2(acc[o][3]);
        float m0 = fmaxf(fmaxf(a0.x,a0.y), fmaxf(a1.x,a1.y)) + b; m0 = fmaxf(m0, 0.f);
        float m1 = fmaxf(fmaxf(a2.x,a2.y), fmaxf(a3.x,a3.y)) + b; m1 = fmaxf(m1, 0.f);
        float* op = out + (size_t)img*outImgStride + (size_t)oc*PH*PH;
        op[(size_t)gy0*PH + gx]     = m0;
        op[(size_t)(gy0+1)*PH + gx] = m1;
    }
}

// ---------------- conv6 (proven) ----------------
template<int IN_H, int TILE_P>
__global__ void conv64_kernel(const float* __restrict__ in,
                              const float* __restrict__ w,
                              const float* __restrict__ bias,
                              float* __restrict__ out,
                              int outImgStride)
{
    constexpr int PH    = IN_H/2;
    constexpr int TILES = PH / TILE_P;
    constexpr int TI    = TILE_P*2 + 2;
    constexpr int POS   = TILE_P*TILE_P;
    constexpr int NT    = POS*8;
    constexpr int CHUNK = 8;

    __shared__ __align__(16) float sIn[CHUNK][TI][TI];
    __shared__ u64 sW[64][CHUNK][9];

    const int tid = threadIdx.x;
    const int pos = tid & (POS-1);
    const int ocg = tid / POS;
    const int py = pos / TILE_P, px = pos % TILE_P;
    const int img = blockIdx.y;
    const int tpy = blockIdx.x / TILES, tpx = blockIdx.x % TILES;
    const int cy0 = tpy*TILE_P*2, cx0 = tpx*TILE_P*2;
    const float* inImg = in + (size_t)img*64*IN_H*IN_H;

    u64 accA[8], accB[8];
    #pragma unroll
    for (int i=0;i<8;i++){ accA[i]=0ull; accB[i]=0ull; }

    for (int ci0 = 0; ci0 < 64; ci0 += CHUNK){
        for (int idx = tid; idx < CHUNK*TI*TI; idx += NT){
            int k = idx/(TI*TI), rem = idx%(TI*TI);
            int r = rem/TI, c = rem%TI;
            int iy = cy0-1+r, ix = cx0-1+c;
            float v = 0.f;
            if (iy>=0 && iy<IN_H && ix>=0 && ix<IN_H)
                v = inImg[(size_t)(ci0+k)*IN_H*IN_H + (size_t)iy*IN_H + ix];
            sIn[k][r][c] = v;
        }
        for (int idx = tid; idx < 64*CHUNK*9; idx += NT){
            int oc = idx/(CHUNK*9), rem = idx%(CHUNK*9);
            int k = rem/9, tt = rem%9;
            float wv = w[(oc*64 + (ci0+k))*9 + tt];
            sW[oc][k][tt] = pk2(wv, wv);
        }
        __syncthreads();

        #pragma unroll
        for (int k=0;k<CHUNK;k++){
            u64 P[4][3];
            #pragma unroll
            for (int r=0;r<4;r++){
                float2 a = *(const float2*)&sIn[k][2*py+r][2*px];
                float2 b = *(const float2*)&sIn[k][2*py+r][2*px+2];
                P[r][0] = pk2(a.x, a.y);
                P[r][1] = pk2(a.y, b.x);
                P[r][2] = pk2(b.x, b.y);
            }
            #pragma unroll
            for (int o=0;o<8;o++){
                const u64* wp = &sW[ocg*8+o][k][0];
                #pragma unroll
                for (int dy=0;dy<3;dy++){
                    #pragma unroll
                    for (int dx=0;dx<3;dx++){
                        u64 wv = wp[dy*3+dx];
                        fma2(accA[o], P[dy][dx],   wv);
                        fma2(accB[o], P[dy+1][dx], wv);
                    }
                }
            }
        }
        __syncthreads();
    }

    const int gy = tpy*TILE_P+py, gx = tpx*TILE_P+px;
    #pragma unroll
    for (int o=0;o<8;o++){
        int oc = ocg*8+o;
        float2 ca = up2(accA[o]); float2 cb = up2(accB[o]);
        float m = fmaxf(fmaxf(ca.x,ca.y), fmaxf(cb.x,cb.y)) + bias[oc];
        m = fmaxf(m, 0.f);
        out[(size_t)img*outImgStride + (size_t)oc*PH*PH + (size_t)gy*PH + gx] = m;
    }
}

// ---------------- small kernels (proven) ----------------
__global__ void zero_kernel(float* __restrict__ p, int n){
    int i = blockIdx.x*256 + threadIdx.x;
    if (i < n) p[i] = 0.f;
}

__global__ void scatter_kernel(const float* __restrict__ feat, int stride, int colOff,
                               const int* __restrict__ ei, int E, int base,
                               float* __restrict__ agg, float* __restrict__ cnt)
{
    int e = blockIdx.x;
    int src = ei[e], dst = ei[E + e];
    const float* f = feat + (size_t)(base+src)*stride + colOff;
    float* a = agg + (size_t)(base+dst)*1024;
    for (int d = threadIdx.x; d < 1024; d += blockDim.x)
        atomicAdd(&a[d], f[d]);
    if (threadIdx.x == 0) atomicAdd(&cnt[base+dst], 1.f);
}

__global__ void combine_kernel(const float* __restrict__ feat, int fstride, int fcolOff,
                               const float* __restrict__ agg, const float* __restrict__ cnt,
                               float* __restrict__ outp, int ostride, int ocolOff)
{
    int i = blockIdx.x*256 + threadIdx.x;
    if (i >= NTOT*1024) return;
    int n = i >> 10, d = i & 1023;
    float c = fmaxf(cnt[n], 1.f);
    float fv = feat[(size_t)n*fstride + fcolOff + d];
    outp[(size_t)n*ostride + ocolOff + d] = (agg[i]/c) * fv;
}

__global__ void gemm_bias_kernel(const float* __restrict__ A, int lda,
                                 const float* __restrict__ W,
                                 const float* __restrict__ bias,
                                 float* __restrict__ C, int M, int K)
{
    __shared__ float sA[16][17];
    __shared__ float sB[16][64];
    int tx = threadIdx.x & 15, ty = threadIdx.x >> 4;
    int n0 = blockIdx.x*64, m0 = blockIdx.y*16;
    float acc[4] = {0.f,0.f,0.f,0.f};
    for (int k0 = 0; k0 < K; k0 += 16){
        int m = m0 + ty;
        sA[ty][tx] = (m < M) ? A[(size_t)m*lda + k0 + tx] : 0.f;
        #pragma unroll
        for (int j=0;j<4;j++)
            sB[ty][tx*4+j] = W[(size_t)(k0+ty)*1024 + n0 + tx*4 + j];
        __syncthreads();
        #pragma unroll
        for (int kk=0;kk<16;kk++){
            float a = sA[ty][kk];
            #pragma unroll
            for (int j=0;j<4;j++) acc[j] += a * sB[kk][tx*4+j];
        }
        __syncthreads();
    }
    int m = m0 + ty;
    if (m < M){
        #pragma unroll
        for (int j=0;j<4;j++)
            C[(size_t)m*1024 + n0 + tx*4 + j] = acc[j] + bias[n0 + tx*4 + j];
    }
}

__global__ void pair_kernel(const float* __restrict__ feat,
                            const float* __restrict__ center,
                            float* __restrict__ bmat)
{
    int s = blockIdx.x, q = blockIdx.y;
    const float* qf = feat + (size_t)(NSUP+q)*1024;
    const float* sf = feat + (size_t)s*1024;
    const float* cf = center + (size_t)(s/5)*1024;
    __shared__ float su[1024];
    __shared__ float rA[256], rB[256], rC[256];
    __shared__ float sS1, sS2;
    int tid = threadIdx.x;

    float S1 = 0.f, S2 = 0.f, M = -1e30f;
    for (int d = tid; d < 1024; d += 256){
        float qd = qf[d], sd = sf[d];
        float df = sd - qd;
        float u = expf(-df*df);
        su[d] = u;
        S2 += u; M = fmaxf(M, u);
        float sc = 0.25f*cf[d] + 0.5f*sd;
        float d2 = sc - qd;
        S1 += expf(-d2*d2);
    }
    rA[tid]=S1; rB[tid]=S2; rC[tid]=M;
    __syncthreads();
    for (int o=128;o>0;o>>=1){
        if (tid<o){ rA[tid]+=rA[tid+o]; rB[tid]+=rB[tid+o]; rC[tid]=fmaxf(rC[tid],rC[tid+o]); }
        __syncthreads();
    }
    if (tid==0){ sS1 = rA[0]; sS2 = rB[0]; }
    float Mv = rC[0];
    __syncthreads();

    float Se = 0.f;
    for (int d = tid; d < 1024; d += 256) Se += expf(su[d] - Mv);
    rA[tid] = Se;
    __syncthreads();
    for (int o=128;o>0;o>>=1){ if (tid<o) rA[tid]+=rA[tid+o]; __syncthreads(); }
    if (tid==0)
        bmat[q*NSUP + s] = sS1 + sS2 - 1024.f*(Mv + logf(rA[0]));
}

__global__ void dis_kernel(const float* __restrict__ bmat,
                           const int* __restrict__ sy,
                           float* __restrict__ dis)
{
    int q = blockIdx.x;
    __shared__ float row[NSUP];
    __shared__ float red[128];
    int tid = threadIdx.x;
    float m = -1e30f;
    for (int s = tid; s < NSUP; s += 128){ row[s] = bmat[q*NSUP+s]; m = fmaxf(m, row[s]); }
    red[tid] = m; __syncthreads();
    for (int o=64;o>0;o>>=1){ if (tid<o) red[tid]=fmaxf(red[tid],red[tid+o]); __syncthreads(); }
    float mv = red[0]; __syncthreads();
    float se = 0.f;
    for (int s = tid; s < NSUP; s += 128) se += expf(row[s]-mv);
    red[tid] = se; __syncthreads();
    for (int o=64;o>0;o>>=1){ if (tid<o) red[tid]+=red[tid+o]; __syncthreads(); }
    float lse = mv + logf(red[0]);
    if (tid < NCLS){
        float sum = 0.f, cntc = 0.f;
        for (int s=0;s<NSUP;s++) if (sy[s]==tid){ sum += row[s]-lse; cntc += 1.f; }
        dis[q*NCLS+tid] = sum / fmaxf(cntc, 1.f);
    }
}

__global__ void center_kernel(const float* __restrict__ feat,
                              const int* __restrict__ sy,
                              const float* __restrict__ center,
                              float* __restrict__ outp)
{
    int c = blockIdx.x;
    int d = blockIdx.y*256 + threadIdx.x;
    __shared__ int ssy[NSUP];
    for (int s = threadIdx.x; s < NSUP; s += 256) ssy[s] = sy[s];
    __syncthreads();
    float sum = 0.f, cnt = 0.f;
    for (int s=0;s<NSUP;s++) if (ssy[s]==c){ sum += feat[(size_t)s*1024 + d]; cnt += 1.f; }
    outp[c*1024 + d] = (sum/fmaxf(cnt,1.f))*0.5f + 0.25f*center[c*1024 + d];
}

__global__ void loss_kernel(const float* __restrict__ dis,
                            const int* __restrict__ qy,
                            float* __restrict__ outp)
{
    __shared__ float sl[32], sa[32];
    int q = threadIdx.x;
    float l = 0.f, a = 0.f;
    if (q < NQRY){
        const float* r = dis + q*NCLS;
        float best = -1e30f; int arg = 0; float m = -1e30f;
        for (int j=0;j<NCLS;j++){
            float v = r[j];
            if (v > best){ best = v; arg = j; }
            m = fmaxf(m, v);
        }
        float se = 0.f;
        for (int j=0;j<NCLS;j++) se += expf(r[j]-m);
        float lse = m + logf(se);
        int y = qy[q];
        l = lse - r[y];
        a = (arg == y) ? 1.f : 0.f;
    }
    sl[threadIdx.x] = l; sa[threadIdx.x] = a;
    __syncthreads();
    if (threadIdx.x == 0){
        float L=0.f, A=0.f;
        for (int i=0;i<32;i++){ L += sl[i]; A += sa[i]; }
        outp[0] = L; outp[1] = A;
    }
}

// ---------------- host launcher ----------------
extern "C" void kernel_launch(void* const* d_in, const int* in_sizes, int n_in,
                              void* d_out, int out_size)
{
    const float* support_x = (const float*)d_in[0];
    const int*   sup_ei    = (const int*)  d_in[1];
    const int*   sup_y     = (const int*)  d_in[3];
    const float* query_x   = (const float*)d_in[4];
    const int*   qry_ei    = (const int*)  d_in[5];
    const int*   qry_y     = (const int*)  d_in[7];
    const float* center    = (const float*)d_in[8];
    const float* cw1       = (const float*)d_in[9];
    const float* cb1       = (const float*)d_in[10];
    const float* cw_rest   = (const float*)d_in[11];
    const float* cb_rest   = (const float*)d_in[12];
    const float* lin2_w    = (const float*)d_in[13];
    const float* lin2_b    = (const float*)d_in[14];
    const float* mlp_w     = (const float*)d_in[15];
    const float* mlp_b     = (const float*)d_in[16];
    float* out = (float*)d_out;

    int Es = in_sizes[1] / 2;
    int Eq = in_sizes[5] / 2;

    float *buf0, *buf1, *cat, *tmp, *h2, *feat, *agg, *cnt, *bmat, *dis;
    __nv_bfloat16 *ahi, *alo, *ahi2, *alo2, *wbp;
    cudaGetSymbolAddress((void**)&buf0, g_buf0);
    cudaGetSymbolAddress((void**)&buf1, g_buf1);
    cudaGetSymbolAddress((void**)&ahi,  g_ahi);
    cudaGetSymbolAddress((void**)&alo,  g_alo);
    cudaGetSymbolAddress((void**)&ahi2, g_ahi2);
    cudaGetSymbolAddress((void**)&alo2, g_alo2);
    cudaGetSymbolAddress((void**)&wbp,  g_wb);
    cudaGetSymbolAddress((void**)&cat,  g_cat);
    cudaGetSymbolAddress((void**)&tmp,  g_tmp);
    cudaGetSymbolAddress((void**)&h2,   g_h2);
    cudaGetSymbolAddress((void**)&feat, g_feat);
    cudaGetSymbolAddress((void**)&agg,  g_agg);
    cudaGetSymbolAddress((void**)&cnt,  g_cnt);
    cudaGetSymbolAddress((void**)&bmat, g_b);
    cudaGetSymbolAddress((void**)&dis,  g_dis);

    const size_t SMEMB = 3*4608*8 + 3*2448*8;                  // conv64e: 169344
    const size_t SMEMT = 55296 + 2*3*(size_t)66*144 + 128;     // tconv: 112448
    static int attr_done = 0;
    if (!attr_done){
        cudaFuncSetAttribute((const void*)tconv_kernel<128,true>, cudaFuncAttributeMaxDynamicSharedMemorySize, (int)SMEMT);
        cudaFuncSetAttribute((const void*)tconv_kernel<64,false>, cudaFuncAttributeMaxDynamicSharedMemorySize, (int)SMEMT);
        cudaFuncSetAttribute(conv64e_kernel<32>, cudaFuncAttributeMaxDynamicSharedMemorySize, (int)SMEMB);
        cudaFuncSetAttribute(conv64e_kernel<16>, cudaFuncAttributeMaxDynamicSharedMemorySize, (int)SMEMB);
        attr_done = 1;
    }

    const int NG = (NTOT*1024 + 255)/256;
    const int WSTR = 64*64*9;

    // capture slot = launch #4 -> tconv<128>
    wb2_kernel<<<(2*73728 + 255)/256, 256>>>(cw_rest, wbp);                         // #1
    conv1n_kernel<<<dim3(512, NTOT), 512>>>(support_x, query_x, cw1, cb1, buf0);    // #2
    tr_kernel<<<dim3(128, NTOT), 256>>>(buf0, ahi, alo);                            // #3
    tconv_kernel<128,true><<<dim3(8, NTOT), 128, SMEMT>>>(ahi, alo, wbp, cb_rest,
                                                          nullptr, ahi2, alo2);     // #4 captured
    tconv_kernel<64,false><<<dim3(4, NTOT), 128, SMEMT>>>(ahi2, alo2, wbp + 73728,
                                                          cb_rest + 64, buf0, nullptr, nullptr);
    conv64e_kernel<32><<<dim3( 4, NTOT), 512, SMEMB>>>(buf0, cw_rest+2*WSTR, cb_rest+128, buf1, 64*16*16);
    conv64e_kernel<16><<<dim3( 1, NTOT), 512, SMEMB>>>(buf1, cw_rest+3*WSTR, cb_rest+192, buf0, 64*8*8);
    conv64_kernel<8,4><<<dim3( 1, NTOT), 128>>>(buf0, cw_rest+4*WSTR, cb_rest+256, cat, 2048);

    zero_kernel<<<NG,256>>>(agg, NTOT*1024);
    zero_kernel<<<1,256>>>(cnt, NTOT);

    // ---- graph conv 1 ----
    scatter_kernel<<<Es,256>>>(cat, 2048, 0, sup_ei, Es, 0,    agg, cnt);
    scatter_kernel<<<Eq,256>>>(cat, 2048, 0, qry_ei, Eq, NSUP, agg, cnt);
    combine_kernel<<<NG,256>>>(cat, 2048, 0, agg, cnt, tmp, 1024, 0);

    gemm_bias_kernel<<<dim3(16,(NTOT+15)/16),256>>>(tmp, 1024, lin2_w, lin2_b, h2, NTOT, 1024);

    // ---- graph conv 2 ----
    zero_kernel<<<NG,256>>>(agg, NTOT*1024);
    zero_kernel<<<1,256>>>(cnt, NTOT);
    scatter_kernel<<<Es,256>>>(h2, 1024, 0, sup_ei, Es, 0,    agg, cnt);
    scatter_kernel<<<Eq,256>>>(h2, 1024, 0, qry_ei, Eq, NSUP, agg, cnt);
    combine_kernel<<<NG,256>>>(h2, 1024, 0, agg, cnt, cat, 2048, 1024);

    gemm_bias_kernel<<<dim3(16,(NTOT+15)/16),256>>>(cat, 2048, mlp_w, mlp_b, feat, NTOT, 2048);

    pair_kernel<<<dim3(NSUP, NQRY), 256>>>(feat, center, bmat);
    dis_kernel<<<NQRY,128>>>(bmat, sup_y, dis);

    center_kernel<<<dim3(NCLS,4),256>>>(feat, sup_y, center, out + 2);
    loss_kernel<<<1,32>>>(dis, qry_y, out);
}

// round 17
// speedup vs baseline: 1.0154x; 1.0154x over previous
#include <cuda_runtime.h>
#include <cuda_bf16.h>
#include <math.h>

typedef unsigned long long u64;
typedef unsigned int u32;

// ---------------- problem constants ----------------
static const int NSUP  = 115;
static const int NQRY  = 23;
static const int NTOT  = 138;
static const int NCLS  = 23;

// ---------------- device scratch ----------------
__device__ float g_buf0[(size_t)NTOT*64*128*128];
__device__ float g_buf1[(size_t)NTOT*64*64*64];
__device__ __nv_bfloat16 g_ahi [(size_t)NTOT*128*130*64];  // conv2 input transposed, hi
__device__ __nv_bfloat16 g_alo [(size_t)NTOT*128*130*64];  // lo
__device__ __nv_bfloat16 g_ahi2[(size_t)NTOT*64*66*64];    // conv3 input transposed (borders stay 0)
__device__ __nv_bfloat16 g_alo2[(size_t)NTOT*64*66*64];
__device__ __nv_bfloat16 g_wb  [2*18*64*64];               // conv2+conv3 weights [L][tp][ci(k)][oc]
__device__ float g_cat [(size_t)NTOT*2048];
__device__ float g_tmp [(size_t)NTOT*1024];
__device__ float g_h2  [(size_t)NTOT*1024];
__device__ float g_feat[(size_t)NTOT*1024];
__device__ float g_agg [(size_t)NTOT*1024];
__device__ float g_cnt [NTOT];
__device__ float g_b   [NQRY*NSUP];
__device__ float g_dis [NQRY*NCLS];

// ---------------- packed f32x2 helpers ----------------
__device__ __forceinline__ u64 pk2(float x, float y){
    u64 r; asm("mov.b64 %0, {%1, %2};" : "=l"(r) : "f"(x), "f"(y)); return r;
}
__device__ __forceinline__ void fma2(u64 &d, u64 a, u64 b){
    asm("fma.rn.f32x2 %0, %1, %2, %0;" : "+l"(d) : "l"(a), "l"(b));
}
__device__ __forceinline__ float2 up2(u64 a){
    float2 r; asm("mov.b64 {%0, %1}, %2;" : "=f"(r.x), "=f"(r.y) : "l"(a)); return r;
}
__device__ __forceinline__ u64 cmp2(u64 a, u64 b){ return (a >> 32) | (b << 32); }

// ---------------- warp-mma + cp.async helpers ----------------
__device__ __forceinline__ void ldsm4(u32* r, u32 addr){
    asm volatile("ldmatrix.sync.aligned.m8n8.x4.shared.b16 {%0,%1,%2,%3}, [%4];"
        : "=r"(r[0]),"=r"(r[1]),"=r"(r[2]),"=r"(r[3]) : "r"(addr));
}
__device__ __forceinline__ void ldsm4t(u32* r, u32 addr){
    asm volatile("ldmatrix.sync.aligned.m8n8.x4.trans.shared.b16 {%0,%1,%2,%3}, [%4];"
        : "=r"(r[0]),"=r"(r[1]),"=r"(r[2]),"=r"(r[3]) : "r"(addr));
}
#define MMA(dd, a, b0, b1) \
    asm volatile("mma.sync.aligned.m16n8k16.row.col.f32.bf16.bf16.f32 " \
        "{%0,%1,%2,%3},{%4,%5,%6,%7},{%8,%9},{%0,%1,%2,%3};" \
        : "+f"((dd)[0]),"+f"((dd)[1]),"+f"((dd)[2]),"+f"((dd)[3]) \
        : "r"((a)[0]),"r"((a)[1]),"r"((a)[2]),"r"((a)[3]), "r"(b0),"r"(b1))
__device__ __forceinline__ void cpa16(u32 s, const void* g){
    asm volatile("cp.async.cg.shared.global [%0], [%1], 16;" :: "r"(s), "l"(g));
}
__device__ __forceinline__ void cpa_commit(){ asm volatile("cp.async.commit_group;"); }
__device__ __forceinline__ void cpa_wait0(){ asm volatile("cp.async.wait_group 0;"); }

// ---------------- prep: weight split for conv2+conv3, layout [L][tp][ci(k)][oc] ----------------
__global__ void wb2_kernel(const float* __restrict__ cwr, __nv_bfloat16* __restrict__ wbp)
{
    int i = blockIdx.x*256 + threadIdx.x;
    if (i >= 2*73728) return;
    int L = i / 73728;
    int r = i % 73728;
    int oc = r & 63, ci = (r>>6)&63, tp = r>>12;
    int tap = tp >> 1, part = tp & 1;
    float v = cwr[(size_t)L*36864 + (oc*64 + ci)*9 + tap];
    __nv_bfloat16 h = __float2bfloat16(v);
    wbp[i] = (part == 0) ? h : __float2bfloat16(v - __bfloat162float(h));
}

// ---------------- prep: transpose conv1 out to [img][y][x+1][ci] bf16 hi/lo ----------------
__global__ void tr_kernel(const float* __restrict__ in,
                          __nv_bfloat16* __restrict__ ahi,
                          __nv_bfloat16* __restrict__ alo)
{
    __shared__ float sT[64][133];
    int y = blockIdx.x, img = blockIdx.y;
    const float* src = in + (size_t)img*64*16384 + y*128;
    for (int e = threadIdx.x; e < 64*130; e += 256){
        int ci = e / 130, xi = e - ci*130;
        int xs = xi - 1;
        float v = ((unsigned)xs < 128u) ? src[(size_t)ci*16384 + xs] : 0.f;
        sT[ci][xi] = v;
    }
    __syncthreads();
    size_t ob = (size_t)(img*128 + y)*130*64;
    for (int e = threadIdx.x; e < 130*64; e += 256){
        int xi = e >> 6, ci = e & 63;
        float v = sT[ci][xi];
        __nv_bfloat16 h = __float2bfloat16(v);
        ahi[ob + e] = h;
        alo[ob + e] = __float2bfloat16(v - __bfloat162float(h));
    }
}

// ---------------- tconv2w: conv2 via mma.sync, 4 warps x M=32 x N=32, cp.async rows ----------------
// ring: row j -> slot j%3; prefetch distance 2 (row y+2 written into dead slot (y-1)%3)
__global__ void __launch_bounds__(128,1)
tconv2w_kernel(const __nv_bfloat16* __restrict__ ahi,
               const __nv_bfloat16* __restrict__ alo,
               const __nv_bfloat16* __restrict__ wbp,
               const float* __restrict__ bias,
               __nv_bfloat16* __restrict__ outHi,
               __nv_bfloat16* __restrict__ outLo)
{
    constexpr u32 SLOT  = 130*144;      // 18720
    constexpr u32 APART = 3*SLOT;       // 56160

    extern __shared__ __align__(16) unsigned char sm[];
    const u32 SB  = (u32)__cvta_generic_to_shared(sm);
    const u32 SMB = 0;
    const u32 SMA = 92160;
    float* sBias = (float*)(sm + SMA + 2*APART);

    const int tid  = threadIdx.x;
    const int warp = tid >> 5;
    const int t    = tid & 31;
    const int half = blockIdx.x;
    const int img  = blockIdx.y;
    const int m0   = warp*32;

    // B: per tp tile [64 k][32 oc], row stride 80B
    const u32* wb32 = (const u32*)wbp;
    for (int e = tid; e < 18432; e += 128){
        int oc2 = e & 15, ci = (e>>4)&63, tp = e>>10;
        u32 v = wb32[(tp*64 + ci)*32 + half*16 + oc2];
        *(u32*)(sm + SMB + (u32)tp*5120 + (u32)ci*80 + (u32)oc2*4) = v;
    }
    if (tid < 32) sBias[t] = bias[half*32 + t];

    const char* gH = (const char*)(ahi + (size_t)img*128*130*64);
    const char* gL = (const char*)(alo + (size_t)img*128*130*64);

    auto cpa_row = [&](int j){
        if ((unsigned)j >= 128u) return;
        u32 slotB = SB + SMA + (u32)(j%3)*SLOT;
        const char* sh = gH + (size_t)j*16640;
        const char* sl = gL + (size_t)j*16640;
        #pragma unroll
        for (int i = 0; i < 9; i++){
            int c = tid + i*128;
            if (c < 1040){
                u32 dst = slotB + (u32)(c>>3)*144 + (u32)(c&7)*16;
                cpa16(dst,         sh + (size_t)c*16);
                cpa16(dst + APART, sl + (size_t)c*16);
            }
        }
    };

    // prologue: rows 0,1
    cpa_row(0); cpa_commit();
    cpa_row(1); cpa_commit();

    const u32 laneA = (u32)((t & 15)*144 + (t >> 4)*16);
    const u32 laneB = (u32)((t & 15)*80  + (t >> 4)*16);
    const int quad = t >> 2, qi = t & 3;
    const bool act = ((quad & 1) == 0);

    float prev[2][4][4];
    #pragma unroll
    for (int mb=0;mb<2;mb++)
        #pragma unroll
        for (int nt=0;nt<4;nt++)
            #pragma unroll
            for (int r=0;r<4;r++) prev[mb][nt][r] = 0.f;

    #pragma unroll 1
    for (int y = 0; y < 128; y++){
        cpa_wait0();
        __syncthreads();

        float d[2][4][4];
        #pragma unroll
        for (int mb=0;mb<2;mb++)
            #pragma unroll
            for (int nt=0;nt<4;nt++)
                #pragma unroll
                for (int r=0;r<4;r++) d[mb][nt][r] = 0.f;

        #pragma unroll
        for (int dy = 0; dy < 3; dy++){
            int iy = y + dy - 1;
            if ((unsigned)iy >= 128u) continue;
            u32 slotBase = SB + SMA + (u32)(iy%3)*SLOT;
            #pragma unroll
            for (int dx = 0; dx < 3; dx++){
                int tp = (dy*3+dx)*2;
                u32 aB = slotBase + (u32)(m0+dx)*144 + laneA;
                u32 bB = SB + SMB + (u32)tp*5120 + laneB;
                #pragma unroll
                for (int ks = 0; ks < 4; ks++){
                    u32 aH0[4], aH1[4], aL0[4], aL1[4];
                    u32 bH0[4], bH1[4], bL0[4], bL1[4];
                    ldsm4 (aH0, aB + ks*32);
                    ldsm4 (aH1, aB + 16*144 + ks*32);
                    ldsm4 (aL0, aB + APART + ks*32);
                    ldsm4 (aL1, aB + APART + 16*144 + ks*32);
                    ldsm4t(bH0, bB + ks*1280);
                    ldsm4t(bH1, bB + ks*1280 + 32);
                    ldsm4t(bL0, bB + 5120 + ks*1280);
                    ldsm4t(bL1, bB + 5120 + ks*1280 + 32);
                    // hi*hi
                    MMA(d[0][0], aH0, bH0[0], bH0[1]);
                    MMA(d[0][1], aH0, bH0[2], bH0[3]);
                    MMA(d[0][2], aH0, bH1[0], bH1[1]);
                    MMA(d[0][3], aH0, bH1[2], bH1[3]);
                    MMA(d[1][0], aH1, bH0[0], bH0[1]);
                    MMA(d[1][1], aH1, bH0[2], bH0[3]);
                    MMA(d[1][2], aH1, bH1[0], bH1[1]);
                    MMA(d[1][3], aH1, bH1[2], bH1[3]);
                    // hi*lo
                    MMA(d[0][0], aH0, bL0[0], bL0[1]);
                    MMA(d[0][1], aH0, bL0[2], bL0[3]);
                    MMA(d[0][2], aH0, bL1[0], bL1[1]);
                    MMA(d[0][3], aH0, bL1[2], bL1[3]);
                    MMA(d[1][0], aH1, bL0[0], bL0[1]);
                    MMA(d[1][1], aH1, bL0[2], bL0[3]);
                    MMA(d[1][2], aH1, bL1[0], bL1[1]);
                    MMA(d[1][3], aH1, bL1[2], bL1[3]);
                    // lo*hi
                    MMA(d[0][0], aL0, bH0[0], bH0[1]);
                    MMA(d[0][1], aL0, bH0[2], bH0[3]);
                    MMA(d[0][2], aL0, bH1[0], bH1[1]);
                    MMA(d[0][3], aL0, bH1[2], bH1[3]);
                    MMA(d[1][0], aL1, bH0[0], bH0[1]);
                    MMA(d[1][1], aL1, bH0[2], bH0[3]);
                    MMA(d[1][2], aL1, bH1[0], bH1[1]);
                    MMA(d[1][3], aL1, bH1[2], bH1[3]);
                }
            }
        }

        // epilogue: x-pair pool via shfl(4), y-pair via registers; odd rows write transposed out
        #pragma unroll
        for (int mb = 0; mb < 2; mb++){
            #pragma unroll
            for (int nt = 0; nt < 4; nt++){
                #pragma unroll
                for (int r = 0; r < 4; r++){
                    float v = d[mb][nt][r];
                    float p = fmaxf(v, __shfl_xor_sync(0xffffffffu, v, 4));
                    if (act){
                        if ((y & 1) == 0){
                            prev[mb][nt][r] = p;
                        } else {
                            int x2  = (m0 + mb*16 + quad + ((r>>1)<<3)) >> 1;
                            int ocl = nt*8 + (qi<<1) + (r&1);
                            float o = fmaxf(prev[mb][nt][r], p) + sBias[ocl];
                            o = fmaxf(o, 0.f);
                            size_t idx = (((size_t)img*64 + (y>>1))*66 + x2+1)*64 + half*32 + ocl;
                            __nv_bfloat16 h = __float2bfloat16(o);
                            outHi[idx] = h;
                            outLo[idx] = __float2bfloat16(o - __bfloat162float(h));
                        }
                    }
                }
            }
        }

        __syncthreads();           // all reads of slot (y-1)%3 done before overwrite
        cpa_row(y+2);              // row y+2 -> slot (y+2)%3 == (y-1)%3 (dead)
        cpa_commit();
    }
}

// ---------------- tconv (R14 proven template) -- used for conv3 ----------------
template<int IN_H, bool OUT_TR>
__global__ void __launch_bounds__(2*IN_H, 1)
tconv_kernel(const __nv_bfloat16* __restrict__ ahi,
             const __nv_bfloat16* __restrict__ alo,
             const __nv_bfloat16* __restrict__ wbp,
             const float* __restrict__ bias,
             float* __restrict__ outF,
             __nv_bfloat16* __restrict__ outHi,
             __nv_bfloat16* __restrict__ outLo)
{
    constexpr int XN      = IN_H + 2;
    constexpr int WARPS   = IN_H/16;
    constexpr int THREADS = 32*WARPS;
    constexpr int PH      = IN_H/2;
    constexpr int ROWU32  = XN*32;
    constexpr int NSTG    = (ROWU32 + THREADS-1)/THREADS;
    constexpr u32 SLOT    = (u32)XN*144;
    constexpr u32 APART   = 3*SLOT;

    extern __shared__ __align__(16) unsigned char sm[];
    const u32 SB = (u32)__cvta_generic_to_shared(sm);
    const u32 SMB = 0;
    const u32 SMA = 92160;
    float* sBias = (float*)(sm + SMA + 2*APART);

    const int tid  = threadIdx.x;
    const int warp = tid >> 5;
    const int t    = tid & 31;
    const int half = blockIdx.x;
    const int img  = blockIdx.y;
    const int m0   = warp*16;

    const u32* wb32 = (const u32*)wbp;
    for (int e = tid; e < 18432; e += THREADS){
        int oc2 = e & 15, ci = (e>>4)&63, tp = e>>10;
        u32 v = wb32[(tp*64 + ci)*32 + half*16 + oc2];
        *(u32*)(sm + SMB + (u32)tp*5120 + (u32)ci*80 + (u32)oc2*4) = v;
    }
    if (tid < 32) sBias[t] = bias[half*32 + t];

    const u32* srcH = (const u32*)(ahi + (size_t)img*IN_H*XN*64);
    const u32* srcL = (const u32*)(alo + (size_t)img*IN_H*XN*64);

    u32 fH[NSTG], fL[NSTG];
    auto stage = [&](int j){
        #pragma unroll
        for (int i = 0; i < NSTG; i++){
            int e = tid + i*THREADS;
            if (e < ROWU32){
                fH[i] = srcH[(size_t)j*ROWU32 + e];
                fL[i] = srcL[(size_t)j*ROWU32 + e];
            }
        }
    };
    auto sts = [&](int j){
        u32 slotB = SMA + (u32)((j+1)%3)*SLOT;
        #pragma unroll
        for (int i = 0; i < NSTG; i++){
            int e = tid + i*THREADS;
            if (e < ROWU32){
                int xi = e >> 5, ci2 = e & 31;
                u32 off = slotB + (u32)xi*144 + (u32)ci2*4;
                *(u32*)(sm + off)         = fH[i];
                *(u32*)(sm + off + APART) = fL[i];
            }
        }
    };

    stage(0); sts(0);
    stage(1); sts(1);
    stage(2);
    __syncthreads();

    const u32 laneA = (u32)((t & 15)*144 + (t >> 4)*16);
    const u32 laneB = (u32)((t & 15)*80  + (t >> 4)*16);
    const int quad = t >> 2, qi = t & 3;
    const bool act = ((quad & 1) == 0);
    float* opF = OUT_TR ? nullptr
               : outF + (size_t)img*64*PH*PH + (size_t)half*32*PH*PH;

    float prev[4][4];
    #pragma unroll
    for (int nt=0;nt<4;nt++)
        #pragma unroll
        for (int r=0;r<4;r++) prev[nt][r] = 0.f;

    #pragma unroll 1
    for (int y = 0; y < IN_H; y++){
        float d[4][4];
        #pragma unroll
        for (int nt=0;nt<4;nt++)
            #pragma unroll
            for (int r=0;r<4;r++) d[nt][r] = 0.f;

        #pragma unroll
        for (int dy = 0; dy < 3; dy++){
            int iy = y + dy - 1;
            if ((unsigned)iy >= (unsigned)IN_H) continue;
            u32 slotBase = SB + SMA + (u32)((y+dy)%3)*SLOT;
            #pragma unroll
            for (int dx = 0; dx < 3; dx++){
                int tp = (dy*3+dx)*2;
                u32 aB = slotBase + (u32)(m0+dx)*144 + laneA;
                u32 bB = SB + SMB + (u32)tp*5120 + laneB;
                #pragma unroll
                for (int ks = 0; ks < 4; ks++){
                    u32 aH[4], aL[4], bH0[4], bH1[4], bL0[4], bL1[4];
                    ldsm4 (aH,  aB + ks*32);
                    ldsm4 (aL,  aB + APART + ks*32);
                    ldsm4t(bH0, bB + ks*1280);
                    ldsm4t(bH1, bB + ks*1280 + 32);
                    ldsm4t(bL0, bB + 5120 + ks*1280);
                    ldsm4t(bL1, bB + 5120 + ks*1280 + 32);
                    MMA(d[0], aH, bH0[0], bH0[1]);
                    MMA(d[1], aH, bH0[2], bH0[3]);
                    MMA(d[2], aH, bH1[0], bH1[1]);
                    MMA(d[3], aH, bH1[2], bH1[3]);
                    MMA(d[0], aH, bL0[0], bL0[1]);
                    MMA(d[1], aH, bL0[2], bL0[3]);
                    MMA(d[2], aH, bL1[0], bL1[1]);
                    MMA(d[3], aH, bL1[2], bL1[3]);
                    MMA(d[0], aL, bH0[0], bH0[1]);
                    MMA(d[1], aL, bH0[2], bH0[3]);
                    MMA(d[2], aL, bH1[0], bH1[1]);
                    MMA(d[3], aL, bH1[2], bH1[3]);
                }
            }
        }

        #pragma unroll
        for (int nt = 0; nt < 4; nt++){
            #pragma unroll
            for (int r = 0; r < 4; r++){
                float v = d[nt][r];
                float p = fmaxf(v, __shfl_xor_sync(0xffffffffu, v, 4));
                if (act){
                    if ((y & 1) == 0){
                        prev[nt][r] = p;
                    } else {
                        int x2  = (m0 + quad + ((r>>1)<<3)) >> 1;
                        int ocl = nt*8 + (qi<<1) + (r&1);
                        float o = fmaxf(prev[nt][r], p) + sBias[ocl];
                        o = fmaxf(o, 0.f);
                        if (OUT_TR){
                            size_t idx = (((size_t)img*PH + (y>>1))*(PH+2) + x2+1)*64 + half*32 + ocl;
                            __nv_bfloat16 h = __float2bfloat16(o);
                            outHi[idx] = h;
                            outLo[idx] = __float2bfloat16(o - __bfloat162float(h));
                        } else {
                            opF[(size_t)ocl*PH*PH + ((size_t)(y>>1))*PH + x2] = o;
                        }
                    }
                }
            }
        }

        __syncthreads();
        if (y + 2 < IN_H) sts(y+2);
        if (y + 3 < IN_H) stage(y+3);
        __syncthreads();
    }
}

// ---------------- conv1n (proven) ----------------
__global__ void __launch_bounds__(512, 2)
conv1n_kernel(const float* __restrict__ sx,
              const float* __restrict__ qx,
              const float* __restrict__ w,
              const float* __restrict__ bias,
              float* __restrict__ out)
{
    __shared__ __align__(16) float sTile[3][10][18];
    __shared__ u64 sW[64][27];

    const int tid = threadIdx.x;
    const int img = blockIdx.y;
    const int tx = blockIdx.x & 15;
    const int ty = blockIdx.x >> 4;
    const int gx0 = tx*16, gy0 = ty*8;
    const float* inImg = (img < NSUP) ? sx + (size_t)img*3*65536
                                      : qx + (size_t)(img-NSUP)*3*65536;

    for (int idx = tid; idx < 540; idx += 512){
        int k = idx/180; int rem = idx - k*180;
        int r = rem/18, c = rem - r*18;
        int iy = gy0 - 1 + r, ix = gx0 - 1 + c;
        float v = 0.f;
        if ((unsigned)iy < 256u && (unsigned)ix < 256u)
            v = inImg[k*65536 + iy*256 + ix];
        sTile[k][r][c] = v;
    }
    for (int idx = tid; idx < 1728; idx += 512){
        float v = w[idx];
        sW[idx/27][idx%27] = pk2(v, v);
    }
    __syncthreads();

    const int oc  = tid >> 3;
    const int sid = tid & 7;
    const u64* tbase = (const u64*)sTile;

    u64 acc[8];
    #pragma unroll
    for (int r = 0; r < 8; r++) acc[r] = 0ull;

    #pragma unroll
    for (int ci = 0; ci < 3; ci++){
        u64 wr[9];
        #pragma unroll
        for (int tt = 0; tt < 9; tt++) wr[tt] = sW[oc][ci*9 + tt];
        #pragma unroll
        for (int tr = 0; tr < 10; tr++){
            u64 T0 = tbase[(ci*10 + tr)*9 + sid];
            u64 T2 = tbase[(ci*10 + tr)*9 + sid + 1];
            u64 T1 = cmp2(T0, T2);
            #pragma unroll
            for (int dy = 0; dy < 3; dy++){
                const int r = tr - dy;
                if (r >= 0 && r < 8){
                    fma2(acc[r], T0, wr[dy*3+0]);
                    fma2(acc[r], T1, wr[dy*3+1]);
                    fma2(acc[r], T2, wr[dy*3+2]);
                }
            }
        }
    }

    float b = bias[oc];
    const int pxl = tx*8 + sid;
    const int py0 = ty*4;
    float* op = out + ((size_t)img*64 + oc)*16384;
    #pragma unroll
    for (int i = 0; i < 4; i++){
        float2 a0 = up2(acc[2*i]), a1 = up2(acc[2*i+1]);
        float m = fmaxf(fmaxf(a0.x, a0.y), fmaxf(a1.x, a1.y)) + b;
        op[(py0 + i)*128 + pxl] = fmaxf(m, 0.f);
    }
}

// ---------------- conv64e (proven): triple-buffered FFMA2 conv ----------------
template<int IN_H>
__global__ void __launch_bounds__(512,1)
conv64e_kernel(const float* __restrict__ in,
               const float* __restrict__ w,
               const float* __restrict__ bias,
               float* __restrict__ out,
               int outImgStride)
{
    constexpr int PH    = IN_H/2;
    constexpr int TILES = PH/8;
    constexpr int TI    = 18;
    constexpr int CHUNK = 8;
    constexpr int HH    = IN_H*IN_H;
    constexpr int PKN   = CHUNK*TI*17;
    constexpr int WN    = 64*CHUNK*9;

    extern __shared__ __align__(16) unsigned char smx[];
    u64* sW  = (u64*)smx;
    u64* sPk = (u64*)(smx + 3*(size_t)WN*8);

    const int tid = threadIdx.x;
    const int pos = tid & 31;
    const int ocg = tid >> 5;
    const int pr  = pos & 3;
    const int px  = pos >> 2;
    const int img = blockIdx.y;
    const int tpy = blockIdx.x / TILES, tpx = blockIdx.x % TILES;
    const int cy0 = tpy*16, cx0 = tpx*16;
    const float* inImg = in + (size_t)img*64*HH;

    int  eoff[5];
    bool ep0[5], ep1[5];
    #pragma unroll
    for (int j=0;j<5;j++){
        int e = tid + j*512;
        bool v = e < PKN;
        int ee = v ? e : 0;
        int k = ee/306, rem = ee - k*306;
        int r = rem/17,  s  = rem - r*17;
        int c0 = (s<9) ? 2*s : 2*(s-9)+1;
        int iy = cy0-1+r, ix0 = cx0-1+c0;
        bool rowok = (unsigned)iy < (unsigned)IN_H;
        ep0[j] = v && rowok && (unsigned)ix0     < (unsigned)IN_H;
        ep1[j] = v && rowok && (unsigned)(ix0+1) < (unsigned)IN_H;
        eoff[j] = k*HH + iy*IN_H + ix0;
    }
    int gwoff[9];
    #pragma unroll
    for (int j=0;j<9;j++){
        int we = tid + j*512;
        int oc = we/72, rem = we - oc*72;
        int k = rem/9,  tt  = rem - k*9;
        gwoff[j] = (oc*64 + k)*9 + tt;
    }

    u64 acc[4][4];
    #pragma unroll
    for (int o=0;o<4;o++)
        #pragma unroll
        for (int cc=0;cc<4;cc++) acc[o][cc] = 0ull;

    float f[5][2], wr[9];
    const float* pIn = inImg;
    const float* pW  = w;

    #pragma unroll
    for (int j=0;j<5;j++){
        f[j][0] = ep0[j] ? pIn[eoff[j]]   : 0.f;
        f[j][1] = ep1[j] ? pIn[eoff[j]+1] : 0.f;
    }
    #pragma unroll
    for (int j=0;j<9;j++) wr[j] = pW[gwoff[j]];
    pIn += CHUNK*HH; pW += 72;

    #pragma unroll
    for (int j=0;j<5;j++){
        int e = tid + j*512;
        if (e < PKN) *(float2*)(sPk + e) = make_float2(f[j][0], f[j][1]);
    }
    #pragma unroll
    for (int j=0;j<9;j++)
        *(float2*)(sW + tid + j*512) = make_float2(wr[j], wr[j]);

    #pragma unroll
    for (int j=0;j<5;j++){
        f[j][0] = ep0[j] ? pIn[eoff[j]]   : 0.f;
        f[j][1] = ep1[j] ? pIn[eoff[j]+1] : 0.f;
    }
    #pragma unroll
    for (int j=0;j<9;j++) wr[j] = pW[gwoff[j]];
    pIn += CHUNK*HH; pW += 72;

    __syncthreads();

    int rb = 0, wb = 1;
    #pragma unroll 1
    for (int c = 0; c < 8; c++){
        if (c < 7){
            u64* pkw = sPk + wb*PKN;
            u64* ww  = sW  + wb*WN;
            #pragma unroll
            for (int j=0;j<5;j++){
                int e = tid + j*512;
                if (e < PKN) *(float2*)(pkw + e) = make_float2(f[j][0], f[j][1]);
            }
            #pragma unroll
            for (int j=0;j<9;j++)
                *(float2*)(ww + tid + j*512) = make_float2(wr[j], wr[j]);
        }
        if (c < 6){
            #pragma unroll
            for (int j=0;j<5;j++){
                f[j][0] = ep0[j] ? pIn[eoff[j]]   : 0.f;
                f[j][1] = ep1[j] ? pIn[eoff[j]+1] : 0.f;
            }
            #pragma unroll
            for (int j=0;j<9;j++) wr[j] = pW[gwoff[j]];
            pIn += CHUNK*HH; pW += 72;
        }

        const u64* pkb = sPk + rb*PKN;
        const u64* wbb = sW  + rb*WN;
        #pragma unroll
        for (int k=0;k<CHUNK;k++){
            const u64* prow = pkb + (k*TI + 4*pr)*17;
            u64 P[6][3];
            #pragma unroll
            for (int r=0;r<6;r++){
                P[r][0] = prow[r*17 + px];
                P[r][1] = prow[r*17 + 9 + px];
                P[r][2] = prow[r*17 + px + 1];
            }
            #pragma unroll
            for (int o=0;o<4;o++){
                const u64* wp = wbb + ((ocg*4+o)*8 + k)*9;
                #pragma unroll
                for (int dy=0;dy<3;dy++){
                    u64 w0 = wp[dy*3+0], w1 = wp[dy*3+1], w2 = wp[dy*3+2];
                    #pragma unroll
                    for (int cc=0;cc<4;cc++) fma2(acc[o][cc], P[cc+dy][0], w0);
                    #pragma unroll
                    for (int cc=0;cc<4;cc++) fma2(acc[o][cc], P[cc+dy][1], w1);
                    #pragma unroll
                    for (int cc=0;cc<4;cc++) fma2(acc[o][cc], P[cc+dy][2], w2);
                }
            }
        }

        if (c == 7) break;
        __syncthreads();
        rb = wb; wb = (wb == 2) ? 0 : wb + 1;
    }

    const int gx  = tpx*8 + px;
    const int gy0 = tpy*8 + 2*pr;
    #pragma unroll
    for (int o=0;o<4;o++){
        int oc = ocg*4 + o;
        float b = bias[oc];
        float2 a0 = up2(acc[o][0]), a1 = up2(acc[o][1]);
        float2 a2 = up2(acc[o][2]), a3 = up2(acc[o][3]);
        float m0 = fmaxf(fmaxf(a0.x,a0.y), fmaxf(a1.x,a1.y)) + b; m0 = fmaxf(m0, 0.f);
        float m1 = fmaxf(fmaxf(a2.x,a2.y), fmaxf(a3.x,a3.y)) + b; m1 = fmaxf(m1, 0.f);
        float* op = out + (size_t)img*outImgStride + (size_t)oc*PH*PH;
        op[(size_t)gy0*PH + gx]     = m0;
        op[(size_t)(gy0+1)*PH + gx] = m1;
    }
}

// ---------------- conv6 (proven) ----------------
template<int IN_H, int TILE_P>
__global__ void conv64_kernel(const float* __restrict__ in,
                              const float* __restrict__ w,
                              const float* __restrict__ bias,
                              float* __restrict__ out,
                              int outImgStride)
{
    constexpr int PH    = IN_H/2;
    constexpr int TILES = PH / TILE_P;
    constexpr int TI    = TILE_P*2 + 2;
    constexpr int POS   = TILE_P*TILE_P;
    constexpr int NT    = POS*8;
    constexpr int CHUNK = 8;

    __shared__ __align__(16) float sIn[CHUNK][TI][TI];
    __shared__ u64 sW[64][CHUNK][9];

    const int tid = threadIdx.x;
    const int pos = tid & (POS-1);
    const int ocg = tid / POS;
    const int py = pos / TILE_P, px = pos % TILE_P;
    const int img = blockIdx.y;
    const int tpy = blockIdx.x / TILES, tpx = blockIdx.x % TILES;
    const int cy0 = tpy*TILE_P*2, cx0 = tpx*TILE_P*2;
    const float* inImg = in + (size_t)img*64*IN_H*IN_H;

    u64 accA[8], accB[8];
    #pragma unroll
    for (int i=0;i<8;i++){ accA[i]=0ull; accB[i]=0ull; }

    for (int ci0 = 0; ci0 < 64; ci0 += CHUNK){
        for (int idx = tid; idx < CHUNK*TI*TI; idx += NT){
            int k = idx/(TI*TI), rem = idx%(TI*TI);
            int r = rem/TI, c = rem%TI;
            int iy = cy0-1+r, ix = cx0-1+c;
            float v = 0.f;
            if (iy>=0 && iy<IN_H && ix>=0 && ix<IN_H)
                v = inImg[(size_t)(ci0+k)*IN_H*IN_H + (size_t)iy*IN_H + ix];
            sIn[k][r][c] = v;
        }
        for (int idx = tid; idx < 64*CHUNK*9; idx += NT){
            int oc = idx/(CHUNK*9), rem = idx%(CHUNK*9);
            int k = rem/9, tt = rem%9;
            float wv = w[(oc*64 + (ci0+k))*9 + tt];
            sW[oc][k][tt] = pk2(wv, wv);
        }
        __syncthreads();

        #pragma unroll
        for (int k=0;k<CHUNK;k++){
            u64 P[4][3];
            #pragma unroll
            for (int r=0;r<4;r++){
                float2 a = *(const float2*)&sIn[k][2*py+r][2*px];
                float2 b = *(const float2*)&sIn[k][2*py+r][2*px+2];
                P[r][0] = pk2(a.x, a.y);
                P[r][1] = pk2(a.y, b.x);
                P[r][2] = pk2(b.x, b.y);
            }
            #pragma unroll
            for (int o=0;o<8;o++){
                const u64* wp = &sW[ocg*8+o][k][0];
                #pragma unroll
                for (int dy=0;dy<3;dy++){
                    #pragma unroll
                    for (int dx=0;dx<3;dx++){
                        u64 wv = wp[dy*3+dx];
                        fma2(accA[o], P[dy][dx],   wv);
                        fma2(accB[o], P[dy+1][dx], wv);
                    }
                }
            }
        }
        __syncthreads();
    }

    const int gy = tpy*TILE_P+py, gx = tpx*TILE_P+px;
    #pragma unroll
    for (int o=0;o<8;o++){
        int oc = ocg*8+o;
        float2 ca = up2(accA[o]); float2 cb = up2(accB[o]);
        float m = fmaxf(fmaxf(ca.x,ca.y), fmaxf(cb.x,cb.y)) + bias[oc];
        m = fmaxf(m, 0.f);
        out[(size_t)img*outImgStride + (size_t)oc*PH*PH + (size_t)gy*PH + gx] = m;
    }
}

// ---------------- small kernels (proven) ----------------
__global__ void zero_kernel(float* __restrict__ p, int n){
    int i = blockIdx.x*256 + threadIdx.x;
    if (i < n) p[i] = 0.f;
}

__global__ void scatter_kernel(const float* __restrict__ feat, int stride, int colOff,
                               const int* __restrict__ ei, int E, int base,
                               float* __restrict__ agg, float* __restrict__ cnt)
{
    int e = blockIdx.x;
    int src = ei[e], dst = ei[E + e];
    const float* f = feat + (size_t)(base+src)*stride + colOff;
    float* a = agg + (size_t)(base+dst)*1024;
    for (int d = threadIdx.x; d < 1024; d += blockDim.x)
        atomicAdd(&a[d], f[d]);
    if (threadIdx.x == 0) atomicAdd(&cnt[base+dst], 1.f);
}

__global__ void combine_kernel(const float* __restrict__ feat, int fstride, int fcolOff,
                               const float* __restrict__ agg, const float* __restrict__ cnt,
                               float* __restrict__ outp, int ostride, int ocolOff)
{
    int i = blockIdx.x*256 + threadIdx.x;
    if (i >= NTOT*1024) return;
    int n = i >> 10, d = i & 1023;
    float c = fmaxf(cnt[n], 1.f);
    float fv = feat[(size_t)n*fstride + fcolOff + d];
    outp[(size_t)n*ostride + ocolOff + d] = (agg[i]/c) * fv;
}

__global__ void gemm_bias_kernel(const float* __restrict__ A, int lda,
                                 const float* __restrict__ W,
                                 const float* __restrict__ bias,
                                 float* __restrict__ C, int M, int K)
{
    __shared__ float sA[16][17];
    __shared__ float sB[16][64];
    int tx = threadIdx.x & 15, ty = threadIdx.x >> 4;
    int n0 = blockIdx.x*64, m0 = blockIdx.y*16;
    float acc[4] = {0.f,0.f,0.f,0.f};
    for (int k0 = 0; k0 < K; k0 += 16){
        int m = m0 + ty;
        sA[ty][tx] = (m < M) ? A[(size_t)m*lda + k0 + tx] : 0.f;
        #pragma unroll
        for (int j=0;j<4;j++)
            sB[ty][tx*4+j] = W[(size_t)(k0+ty)*1024 + n0 + tx*4 + j];
        __syncthreads();
        #pragma unroll
        for (int kk=0;kk<16;kk++){
            float a = sA[ty][kk];
            #pragma unroll
            for (int j=0;j<4;j++) acc[j] += a * sB[kk][tx*4+j];
        }
        __syncthreads();
    }
    int m = m0 + ty;
    if (m < M){
        #pragma unroll
        for (int j=0;j<4;j++)
            C[(size_t)m*1024 + n0 + tx*4 + j] = acc[j] + bias[n0 + tx*4 + j];
    }
}

__global__ void pair_kernel(const float* __restrict__ feat,
                            const float* __restrict__ center,
                            float* __restrict__ bmat)
{
    int s = blockIdx.x, q = blockIdx.y;
    const float* qf = feat + (size_t)(NSUP+q)*1024;
    const float* sf = feat + (size_t)s*1024;
    const float* cf = center + (size_t)(s/5)*1024;
    __shared__ float su[1024];
    __shared__ float rA[256], rB[256], rC[256];
    __shared__ float sS1, sS2;
    int tid = threadIdx.x;

    float S1 = 0.f, S2 = 0.f, M = -1e30f;
    for (int d = tid; d < 1024; d += 256){
        float qd = qf[d], sd = sf[d];
        float df = sd - qd;
        float u = expf(-df*df);
        su[d] = u;
        S2 += u; M = fmaxf(M, u);
        float sc = 0.25f*cf[d] + 0.5f*sd;
        float d2 = sc - qd;
        S1 += expf(-d2*d2);
    }
    rA[tid]=S1; rB[tid]=S2; rC[tid]=M;
    __syncthreads();
    for (int o=128;o>0;o>>=1){
        if (tid<o){ rA[tid]+=rA[tid+o]; rB[tid]+=rB[tid+o]; rC[tid]=fmaxf(rC[tid],rC[tid+o]); }
        __syncthreads();
    }
    if (tid==0){ sS1 = rA[0]; sS2 = rB[0]; }
    float Mv = rC[0];
    __syncthreads();

    float Se = 0.f;
    for (int d = tid; d < 1024; d += 256) Se += expf(su[d] - Mv);
    rA[tid] = Se;
    __syncthreads();
    for (int o=128;o>0;o>>=1){ if (tid<o) rA[tid]+=rA[tid+o]; __syncthreads(); }
    if (tid==0)
        bmat[q*NSUP + s] = sS1 + sS2 - 1024.f*(Mv + logf(rA[0]));
}

__global__ void dis_kernel(const float* __restrict__ bmat,
                           const int* __restrict__ sy,
                           float* __restrict__ dis)
{
    int q = blockIdx.x;
    __shared__ float row[NSUP];
    __shared__ float red[128];
    int tid = threadIdx.x;
    float m = -1e30f;
    for (int s = tid; s < NSUP; s += 128){ row[s] = bmat[q*NSUP+s]; m = fmaxf(m, row[s]); }
    red[tid] = m; __syncthreads();
    for (int o=64;o>0;o>>=1){ if (tid<o) red[tid]=fmaxf(red[tid],red[tid+o]); __syncthreads(); }
    float mv = red[0]; __syncthreads();
    float se = 0.f;
    for (int s = tid; s < NSUP; s += 128) se += expf(row[s]-mv);
    red[tid] = se; __syncthreads();
    for (int o=64;o>0;o>>=1){ if (tid<o) red[tid]+=red[tid+o]; __syncthreads(); }
    float lse = mv + logf(red[0]);
    if (tid < NCLS){
        float sum = 0.f, cntc = 0.f;
        for (int s=0;s<NSUP;s++) if (sy[s]==tid){ sum += row[s]-lse; cntc += 1.f; }
        dis[q*NCLS+tid] = sum / fmaxf(cntc, 1.f);
    }
}

__global__ void center_kernel(const float* __restrict__ feat,
                              const int* __restrict__ sy,
                              const float* __restrict__ center,
                              float* __restrict__ outp)
{
    int c = blockIdx.x;
    int d = blockIdx.y*256 + threadIdx.x;
    __shared__ int ssy[NSUP];
    for (int s = threadIdx.x; s < NSUP; s += 256) ssy[s] = sy[s];
    __syncthreads();
    float sum = 0.f, cnt = 0.f;
    for (int s=0;s<NSUP;s++) if (ssy[s]==c){ sum += feat[(size_t)s*1024 + d]; cnt += 1.f; }
    outp[c*1024 + d] = (sum/fmaxf(cnt,1.f))*0.5f + 0.25f*center[c*1024 + d];
}

__global__ void loss_kernel(const float* __restrict__ dis,
                            const int* __restrict__ qy,
                            float* __restrict__ outp)
{
    __shared__ float sl[32], sa[32];
    int q = threadIdx.x;
    float l = 0.f, a = 0.f;
    if (q < NQRY){
        const float* r = dis + q*NCLS;
        float best = -1e30f; int arg = 0; float m = -1e30f;
        for (int j=0;j<NCLS;j++){
            float v = r[j];
            if (v > best){ best = v; arg = j; }
            m = fmaxf(m, v);
        }
        float se = 0.f;
        for (int j=0;j<NCLS;j++) se += expf(r[j]-m);
        float lse = m + logf(se);
        int y = qy[q];
        l = lse - r[y];
        a = (arg == y) ? 1.f : 0.f;
    }
    sl[threadIdx.x] = l; sa[threadIdx.x] = a;
    __syncthreads();
    if (threadIdx.x == 0){
        float L=0.f, A=0.f;
        for (int i=0;i<32;i++){ L += sl[i]; A += sa[i]; }
        outp[0] = L; outp[1] = A;
    }
}

// ---------------- host launcher ----------------
extern "C" void kernel_launch(void* const* d_in, const int* in_sizes, int n_in,
                              void* d_out, int out_size)
{
    const float* support_x = (const float*)d_in[0];
    const int*   sup_ei    = (const int*)  d_in[1];
    const int*   sup_y     = (const int*)  d_in[3];
    const float* query_x   = (const float*)d_in[4];
    const int*   qry_ei    = (const int*)  d_in[5];
    const int*   qry_y     = (const int*)  d_in[7];
    const float* center    = (const float*)d_in[8];
    const float* cw1       = (const float*)d_in[9];
    const float* cb1       = (const float*)d_in[10];
    const float* cw_rest   = (const float*)d_in[11];
    const float* cb_rest   = (const float*)d_in[12];
    const float* lin2_w    = (const float*)d_in[13];
    const float* lin2_b    = (const float*)d_in[14];
    const float* mlp_w     = (const float*)d_in[15];
    const float* mlp_b     = (const float*)d_in[16];
    float* out = (float*)d_out;

    int Es = in_sizes[1] / 2;
    int Eq = in_sizes[5] / 2;

    float *buf0, *buf1, *cat, *tmp, *h2, *feat, *agg, *cnt, *bmat, *dis;
    __nv_bfloat16 *ahi, *alo, *ahi2, *alo2, *wbp;
    cudaGetSymbolAddress((void**)&buf0, g_buf0);
    cudaGetSymbolAddress((void**)&buf1, g_buf1);
    cudaGetSymbolAddress((void**)&ahi,  g_ahi);
    cudaGetSymbolAddress((void**)&alo,  g_alo);
    cudaGetSymbolAddress((void**)&ahi2, g_ahi2);
    cudaGetSymbolAddress((void**)&alo2, g_alo2);
    cudaGetSymbolAddress((void**)&wbp,  g_wb);
    cudaGetSymbolAddress((void**)&cat,  g_cat);
    cudaGetSymbolAddress((void**)&tmp,  g_tmp);
    cudaGetSymbolAddress((void**)&h2,   g_h2);
    cudaGetSymbolAddress((void**)&feat, g_feat);
    cudaGetSymbolAddress((void**)&agg,  g_agg);
    cudaGetSymbolAddress((void**)&cnt,  g_cnt);
    cudaGetSymbolAddress((void**)&bmat, g_b);
    cudaGetSymbolAddress((void**)&dis,  g_dis);

    const size_t SMEMB  = 3*4608*8 + 3*2448*8;                 // conv64e: 169344
    const size_t SMEMW  = 92160 + 2*3*(size_t)130*144 + 128;   // tconv2w: 204608
    const size_t SMEMT3 = 92160 + 2*3*(size_t)66*144  + 128;   // tconv<64>: 149312
    static int attr_done = 0;
    if (!attr_done){
        cudaFuncSetAttribute((const void*)tconv2w_kernel,          cudaFuncAttributeMaxDynamicSharedMemorySize, (int)SMEMW);
        cudaFuncSetAttribute((const void*)tconv_kernel<64,false>,  cudaFuncAttributeMaxDynamicSharedMemorySize, (int)SMEMT3);
        cudaFuncSetAttribute(conv64e_kernel<32>, cudaFuncAttributeMaxDynamicSharedMemorySize, (int)SMEMB);
        cudaFuncSetAttribute(conv64e_kernel<16>, cudaFuncAttributeMaxDynamicSharedMemorySize, (int)SMEMB);
        attr_done = 1;
    }

    const int NG = (NTOT*1024 + 255)/256;
    const int WSTR = 64*64*9;

    // capture slot = launch #4 -> tconv2w
    wb2_kernel<<<(2*73728 + 255)/256, 256>>>(cw_rest, wbp);                         // #1
    conv1n_kernel<<<dim3(512, NTOT), 512>>>(support_x, query_x, cw1, cb1, buf0);    // #2
    tr_kernel<<<dim3(128, NTOT), 256>>>(buf0, ahi, alo);                            // #3
    tconv2w_kernel<<<dim3(2, NTOT), 128, SMEMW>>>(ahi, alo, wbp, cb_rest,
                                                  ahi2, alo2);                      // #4 captured
    tconv_kernel<64,false><<<dim3(2, NTOT), 128, SMEMT3>>>(ahi2, alo2, wbp + 73728,
                                                           cb_rest + 64, buf0, nullptr, nullptr);
    conv64e_kernel<32><<<dim3( 4, NTOT), 512, SMEMB>>>(buf0, cw_rest+2*WSTR, cb_rest+128, buf1, 64*16*16);
    conv64e_kernel<16><<<dim3( 1, NTOT), 512, SMEMB>>>(buf1, cw_rest+3*WSTR, cb_rest+192, buf0, 64*8*8);
    conv64_kernel<8,4><<<dim3( 1, NTOT), 128>>>(buf0, cw_rest+4*WSTR, cb_rest+256, cat, 2048);

    zero_kernel<<<NG,256>>>(agg, NTOT*1024);
    zero_kernel<<<1,256>>>(cnt, NTOT);

    // ---- graph conv 1 ----
    scatter_kernel<<<Es,256>>>(cat, 2048, 0, sup_ei, Es, 0,    agg, cnt);
    scatter_kernel<<<Eq,256>>>(cat, 2048, 0, qry_ei, Eq, NSUP, agg, cnt);
    combine_kernel<<<NG,256>>>(cat, 2048, 0, agg, cnt, tmp, 1024, 0);

    gemm_bias_kernel<<<dim3(16,(NTOT+15)/16),256>>>(tmp, 1024, lin2_w, lin2_b, h2, NTOT, 1024);

    // ---- graph conv 2 ----
    zero_kernel<<<NG,256>>>(agg, NTOT*1024);
    zero_kernel<<<1,256>>>(cnt, NTOT);
    scatter_kernel<<<Es,256>>>(h2, 1024, 0, sup_ei, Es, 0,    agg, cnt);
    scatter_kernel<<<Eq,256>>>(h2, 1024, 0, qry_ei, Eq, NSUP, agg, cnt);
    combine_kernel<<<NG,256>>>(h2, 1024, 0, agg, cnt, cat, 2048, 1024);

    gemm_bias_kernel<<<dim3(16,(NTOT+15)/16),256>>>(cat, 2048, mlp_w, mlp_b, feat, NTOT, 2048);

    pair_kernel<<<dim3(NSUP, NQRY), 256>>>(feat, center, bmat);
    dis_kernel<<<NQRY,128>>>(bmat, sup_y, dis);

    center_kernel<<<dim3(NCLS,4),256>>>(feat, sup_y, center, out + 2);
    loss_kernel<<<1,32>>>(dis, qry_y, out);
}